// round 2
// baseline (speedup 1.0000x reference)
#include <cuda_runtime.h>
#include <cstdint>

#define LC 1024
#define CS 768
#define NH 16
#define DH 48
#define CP 128

typedef unsigned long long ull;

// ---- scratch (device globals; module-load allocation, sanctioned) ----
__device__ float g_Q[LC * CS];
__device__ float g_K[LC * CS];
__device__ float g_V[LC * CS];
__device__ float g_gate[LC * CS];
__device__ float g_ctx[LC * CS];
__device__ float g_attn_fallback[NH * LC * LC];
__device__ int   g_mask_is_u8;

// ---- f32x2 helpers (FFMA2 path: 2x fp32 FMA throughput on sm_103a) ----
__device__ __forceinline__ ull ffma2(ull a, ull b, ull c) {
    ull d;
    asm("fma.rn.f32x2 %0,%1,%2,%3;" : "=l"(d) : "l"(a), "l"(b), "l"(c));
    return d;
}
__device__ __forceinline__ ull pack2(float lo, float hi) {
    ull r;
    asm("mov.b64 %0,{%1,%2};" : "=l"(r) : "f"(lo), "f"(hi));
    return r;
}
__device__ __forceinline__ void unpack2(ull v, float& lo, float& hi) {
    asm("mov.b64 {%0,%1},%2;" : "=f"(lo), "=f"(hi) : "l"(v));
}

// =====================================================================
// K0: mask dtype detector. int32 bool data => every u32 word is 0/1.
// uint8 bool data read as u32 packs 4 bools => words >1 appear w.h.p.
// =====================================================================
__global__ void k_detect(const unsigned int* __restrict__ m)
{
    __shared__ int s;
    if (threadIdx.x == 0) s = 0;
    __syncthreads();
    int bad = 0;
    for (int i = threadIdx.x; i < 1024; i += blockDim.x)
        if (m[i] > 1u) bad = 1;
    if (bad) atomicOr(&s, 1);
    __syncthreads();
    if (threadIdx.x == 0) g_mask_is_u8 = s;
}

// =====================================================================
// K1: fused projections  X = S @ [Wq|Wk|Wv|Wg] + bias  (M=1024,N=3072,K=768)
// =====================================================================
__global__ void __launch_bounds__(256) k_proj(
    const float* __restrict__ S,
    const float* __restrict__ Wq, const float* __restrict__ bq,
    const float* __restrict__ Wk, const float* __restrict__ bk,
    const float* __restrict__ Wv, const float* __restrict__ bv,
    const float* __restrict__ Wg, const float* __restrict__ bg)
{
    __shared__ __align__(16) float  As[16 * 128];   // [kk][m]
    __shared__ __align__(16) float2 Bs[16 * 128];   // [kk][n] duplicated

    int bn = blockIdx.x;
    int wi = bn / 6;
    int n0 = (bn % 6) * 128;
    int m0 = blockIdx.y * 128;

    const float* W  = wi == 0 ? Wq : wi == 1 ? Wk : wi == 2 ? Wv : Wg;
    const float* bb = wi == 0 ? bq : wi == 1 ? bk : wi == 2 ? bv : bg;
    float*       dst = wi == 0 ? g_Q : wi == 1 ? g_K : wi == 2 ? g_V : g_gate;

    int t = threadIdx.x, tx = t & 15, ty = t >> 4;

    ull acc[4][8];
#pragma unroll
    for (int p = 0; p < 4; p++)
#pragma unroll
        for (int j = 0; j < 8; j++) acc[p][j] = 0ull;

    for (int k0 = 0; k0 < CS; k0 += 16) {
#pragma unroll
        for (int l = 0; l < 2; l++) {
            int idx = l * 256 + t, row = idx >> 2, kq = idx & 3;
            float4 v = *(const float4*)(S + (size_t)(m0 + row) * CS + k0 + kq * 4);
            As[(kq * 4 + 0) * 128 + row] = v.x;
            As[(kq * 4 + 1) * 128 + row] = v.y;
            As[(kq * 4 + 2) * 128 + row] = v.z;
            As[(kq * 4 + 3) * 128 + row] = v.w;
        }
#pragma unroll
        for (int l = 0; l < 2; l++) {
            int idx = l * 256 + t, kk = idx >> 5, nq = idx & 31;
            float4 v = *(const float4*)(W + (size_t)(k0 + kk) * CS + n0 + nq * 4);
            Bs[kk * 128 + nq * 4 + 0] = make_float2(v.x, v.x);
            Bs[kk * 128 + nq * 4 + 1] = make_float2(v.y, v.y);
            Bs[kk * 128 + nq * 4 + 2] = make_float2(v.z, v.z);
            Bs[kk * 128 + nq * 4 + 3] = make_float2(v.w, v.w);
        }
        __syncthreads();
#pragma unroll
        for (int kk = 0; kk < 16; kk++) {
            const ull* Ap = (const ull*)(As + kk * 128);
            const ull* Bp = (const ull*)(Bs + kk * 128);
            ull a2[4], b2[8];
#pragma unroll
            for (int p = 0; p < 4; p++) a2[p] = Ap[ty * 4 + p];
#pragma unroll
            for (int j = 0; j < 8; j++) b2[j] = Bp[tx + 16 * j];
#pragma unroll
            for (int p = 0; p < 4; p++)
#pragma unroll
                for (int j = 0; j < 8; j++) acc[p][j] = ffma2(a2[p], b2[j], acc[p][j]);
        }
        __syncthreads();
    }

#pragma unroll
    for (int j = 0; j < 8; j++) {
        int col = n0 + tx + 16 * j;
        float b = bb[col];
#pragma unroll
        for (int p = 0; p < 4; p++) {
            float lo, hi;
            unpack2(acc[p][j], lo, hi);
            lo += b; hi += b;
            if (wi == 3) {
                lo = 1.f / (1.f + __expf(-lo));
                hi = 1.f / (1.f + __expf(-hi));
            }
            int row = m0 + ty * 8 + 2 * p;
            dst[(size_t)row * CS + col]       = lo;
            dst[(size_t)(row + 1) * CS + col] = hi;
        }
    }
}

// =====================================================================
// K2: base logits = z@Wz + dist + prior, masked -> -1e30, layout [h][i][j]
// =====================================================================
__global__ void __launch_bounds__(128) k_pairbias(
    const float* __restrict__ z, const void* __restrict__ maskp,
    const float* __restrict__ dist, const float* __restrict__ prior,
    const float* __restrict__ Wz, float* __restrict__ A)
{
    __shared__ __align__(16) float2 w2[128 * 8];   // [c][head-pair]
    __shared__ float tr[16][128];

    int i = blockIdx.x, jt = blockIdx.y;
    int t = threadIdx.x;
    int j = jt * 128 + t;

    {
        const float4* wz4 = (const float4*)(Wz + t * 16);
        float4 a = wz4[0], b = wz4[1], c = wz4[2], d = wz4[3];
        w2[t * 8 + 0] = make_float2(a.x, a.y);
        w2[t * 8 + 1] = make_float2(a.z, a.w);
        w2[t * 8 + 2] = make_float2(b.x, b.y);
        w2[t * 8 + 3] = make_float2(b.z, b.w);
        w2[t * 8 + 4] = make_float2(c.x, c.y);
        w2[t * 8 + 5] = make_float2(c.z, c.w);
        w2[t * 8 + 6] = make_float2(d.x, d.y);
        w2[t * 8 + 7] = make_float2(d.z, d.w);
    }
    __syncthreads();

    ull acc[8];
#pragma unroll
    for (int hp = 0; hp < 8; hp++) acc[hp] = 0ull;

    const float4* zp = (const float4*)(z + ((size_t)i * LC + j) * CP);
    const ull* wp = (const ull*)w2;
#pragma unroll 8
    for (int c4 = 0; c4 < 32; c4++) {
        float4 v = zp[c4];
        float vs[4] = {v.x, v.y, v.z, v.w};
#pragma unroll
        for (int u = 0; u < 4; u++) {
            ull zz = pack2(vs[u], vs[u]);
            const ull* wrow = wp + (c4 * 4 + u) * 8;
#pragma unroll
            for (int hp = 0; hp < 8; hp++) acc[hp] = ffma2(zz, wrow[hp], acc[hp]);
        }
    }

    int ij = i * LC + j;
    float bias[16];
#pragma unroll
    for (int hp = 0; hp < 8; hp++) unpack2(acc[hp], bias[2 * hp], bias[2 * hp + 1]);

    const float4* dv = (const float4*)(dist + (size_t)ij * 16);
    float4 d0 = dv[0], d1 = dv[1], d2 = dv[2], d3 = dv[3];
    float db[16] = {d0.x, d0.y, d0.z, d0.w, d1.x, d1.y, d1.z, d1.w,
                    d2.x, d2.y, d2.z, d2.w, d3.x, d3.y, d3.z, d3.w};
    float pr = prior[ij];

    bool mv;
    if (g_mask_is_u8)
        mv = ((const unsigned char*)maskp)[ij] != 0;
    else
        mv = ((const int*)maskp)[ij] != 0;

#pragma unroll
    for (int hh = 0; hh < 16; hh++) {
        float vv = bias[hh] + db[hh] + pr;
        tr[hh][t] = mv ? vv : -1e30f;
    }
    __syncthreads();
#pragma unroll
    for (int hh = 0; hh < 16; hh++)
        A[((size_t)hh * LC + i) * LC + jt * 128 + t] = tr[hh][t];
}

// =====================================================================
// K3a: logits += scale * Q_h K_h^T   (16 GEMMs 1024x1024x48), 64x64 tiles
// =====================================================================
#define QK_SCALE 0.14433756729740643f   // 1/sqrt(48)

__global__ void __launch_bounds__(256) k_qk(float* __restrict__ A)
{
    __shared__ __align__(16) float  Qs[48 * 66];
    __shared__ __align__(16) float2 Ks[48 * 65];

    int j0 = blockIdx.x * 64, i0 = blockIdx.y * 64, h = blockIdx.z;
    int t = threadIdx.x;

#pragma unroll
    for (int l = 0; l < 12; l++) {
        int idx = l * 256 + t;
        int row = idx / 48, k = idx - row * 48;
        Qs[k * 66 + row] = g_Q[(size_t)(i0 + row) * CS + h * DH + k] * QK_SCALE;
        float kv = g_K[(size_t)(j0 + row) * CS + h * DH + k];
        Ks[k * 65 + row] = make_float2(kv, kv);
    }
    __syncthreads();

    int tx = t & 15, ty = t >> 4;
    ull acc[2][4];
#pragma unroll
    for (int p = 0; p < 2; p++)
#pragma unroll
        for (int c = 0; c < 4; c++) acc[p][c] = 0ull;

#pragma unroll
    for (int k = 0; k < 48; k++) {
        const ull* Qp = (const ull*)(Qs + k * 66);
        const ull* Kp = (const ull*)(Ks + k * 65);
        ull a2[2], b2[4];
        a2[0] = Qp[ty * 2];
        a2[1] = Qp[ty * 2 + 1];
#pragma unroll
        for (int c = 0; c < 4; c++) b2[c] = Kp[tx + 16 * c];
#pragma unroll
        for (int p = 0; p < 2; p++)
#pragma unroll
            for (int c = 0; c < 4; c++) acc[p][c] = ffma2(a2[p], b2[c], acc[p][c]);
    }

#pragma unroll
    for (int p = 0; p < 2; p++) {
        int r0 = i0 + ty * 4 + 2 * p;
        float* C0 = A + ((size_t)h * LC + r0) * LC;
        float* C1 = C0 + LC;
#pragma unroll
        for (int c = 0; c < 4; c++) {
            int col = j0 + tx + 16 * c;
            float lo, hi;
            unpack2(acc[p][c], lo, hi);
            C0[col] += lo;
            C1[col] += hi;
        }
    }
}

// =====================================================================
// K3b: rowwise softmax in place, block per (h,i) row
// =====================================================================
__global__ void __launch_bounds__(128) k_softmax(float* __restrict__ A)
{
    size_t r = blockIdx.x;
    float* row = A + r * LC;
    int t = threadIdx.x;
    float4 v0 = ((float4*)row)[2 * t], v1 = ((float4*)row)[2 * t + 1];

    float mx = fmaxf(fmaxf(fmaxf(v0.x, v0.y), fmaxf(v0.z, v0.w)),
                     fmaxf(fmaxf(v1.x, v1.y), fmaxf(v1.z, v1.w)));
#pragma unroll
    for (int o = 16; o; o >>= 1) mx = fmaxf(mx, __shfl_xor_sync(0xffffffffu, mx, o));
    __shared__ float sm[4], ss[4];
    if ((t & 31) == 0) sm[t >> 5] = mx;
    __syncthreads();
    mx = fmaxf(fmaxf(sm[0], sm[1]), fmaxf(sm[2], sm[3]));

    v0.x = __expf(v0.x - mx); v0.y = __expf(v0.y - mx);
    v0.z = __expf(v0.z - mx); v0.w = __expf(v0.w - mx);
    v1.x = __expf(v1.x - mx); v1.y = __expf(v1.y - mx);
    v1.z = __expf(v1.z - mx); v1.w = __expf(v1.w - mx);
    float s = v0.x + v0.y + v0.z + v0.w + v1.x + v1.y + v1.z + v1.w;
#pragma unroll
    for (int o = 16; o; o >>= 1) s += __shfl_xor_sync(0xffffffffu, s, o);
    if ((t & 31) == 0) ss[t >> 5] = s;
    __syncthreads();
    s = ss[0] + ss[1] + ss[2] + ss[3];

    float inv = 1.f / s;
    v0.x *= inv; v0.y *= inv; v0.z *= inv; v0.w *= inv;
    v1.x *= inv; v1.y *= inv; v1.z *= inv; v1.w *= inv;
    ((float4*)row)[2 * t] = v0;
    ((float4*)row)[2 * t + 1] = v1;
}

// =====================================================================
// K4: ctx = attn @ V per head
// =====================================================================
__global__ void __launch_bounds__(256) k_av(const float* __restrict__ A)
{
    __shared__ __align__(16) float  As[32 * 130];
    __shared__ __align__(16) float2 Vs[32 * 49];

    int i0 = blockIdx.x * 128, h = blockIdx.y;
    int t = threadIdx.x, tx = t & 15, ty = t >> 4;

    ull acc[4][3];
#pragma unroll
    for (int p = 0; p < 4; p++)
#pragma unroll
        for (int c = 0; c < 3; c++) acc[p][c] = 0ull;

    for (int j0 = 0; j0 < LC; j0 += 32) {
#pragma unroll
        for (int l = 0; l < 4; l++) {
            int idx = l * 256 + t, row = idx >> 3, jq = idx & 7;
            float4 v = *(const float4*)(A + ((size_t)h * LC + i0 + row) * LC + j0 + jq * 4);
            As[(jq * 4 + 0) * 130 + row] = v.x;
            As[(jq * 4 + 1) * 130 + row] = v.y;
            As[(jq * 4 + 2) * 130 + row] = v.z;
            As[(jq * 4 + 3) * 130 + row] = v.w;
        }
#pragma unroll
        for (int l = 0; l < 6; l++) {
            int idx = l * 256 + t, kk = idx / 48, d = idx - kk * 48;
            float vv = g_V[(size_t)(j0 + kk) * CS + h * DH + d];
            Vs[kk * 49 + d] = make_float2(vv, vv);
        }
        __syncthreads();
#pragma unroll
        for (int kk = 0; kk < 32; kk++) {
            const ull* Ap = (const ull*)(As + kk * 130);
            const ull* Vp = (const ull*)(Vs + kk * 49);
            ull a2[4], b2[3];
#pragma unroll
            for (int p = 0; p < 4; p++) a2[p] = Ap[ty * 4 + p];
#pragma unroll
            for (int c = 0; c < 3; c++) b2[c] = Vp[tx * 3 + c];
#pragma unroll
            for (int p = 0; p < 4; p++)
#pragma unroll
                for (int c = 0; c < 3; c++) acc[p][c] = ffma2(a2[p], b2[c], acc[p][c]);
        }
        __syncthreads();
    }

#pragma unroll
    for (int p = 0; p < 4; p++) {
        int r = i0 + ty * 8 + 2 * p;
#pragma unroll
        for (int c = 0; c < 3; c++) {
            float lo, hi;
            unpack2(acc[p][c], lo, hi);
            g_ctx[(size_t)r * CS + h * DH + tx * 3 + c]       = lo;
            g_ctx[(size_t)(r + 1) * CS + h * DH + tx * 3 + c] = hi;
        }
    }
}

// =====================================================================
// K5: y = gate * (ctx @ Wo + bo)
// =====================================================================
__global__ void __launch_bounds__(256) k_out(
    const float* __restrict__ Wo, const float* __restrict__ bo, float* __restrict__ Y)
{
    __shared__ __align__(16) float  As[16 * 128];
    __shared__ __align__(16) float2 Bs[16 * 128];

    int n0 = blockIdx.x * 128;
    int m0 = blockIdx.y * 128;
    int t = threadIdx.x, tx = t & 15, ty = t >> 4;

    ull acc[4][8];
#pragma unroll
    for (int p = 0; p < 4; p++)
#pragma unroll
        for (int j = 0; j < 8; j++) acc[p][j] = 0ull;

    for (int k0 = 0; k0 < CS; k0 += 16) {
#pragma unroll
        for (int l = 0; l < 2; l++) {
            int idx = l * 256 + t, row = idx >> 2, kq = idx & 3;
            float4 v = *(const float4*)(g_ctx + (size_t)(m0 + row) * CS + k0 + kq * 4);
            As[(kq * 4 + 0) * 128 + row] = v.x;
            As[(kq * 4 + 1) * 128 + row] = v.y;
            As[(kq * 4 + 2) * 128 + row] = v.z;
            As[(kq * 4 + 3) * 128 + row] = v.w;
        }
#pragma unroll
        for (int l = 0; l < 2; l++) {
            int idx = l * 256 + t, kk = idx >> 5, nq = idx & 31;
            float4 v = *(const float4*)(Wo + (size_t)(k0 + kk) * CS + n0 + nq * 4);
            Bs[kk * 128 + nq * 4 + 0] = make_float2(v.x, v.x);
            Bs[kk * 128 + nq * 4 + 1] = make_float2(v.y, v.y);
            Bs[kk * 128 + nq * 4 + 2] = make_float2(v.z, v.z);
            Bs[kk * 128 + nq * 4 + 3] = make_float2(v.w, v.w);
        }
        __syncthreads();
#pragma unroll
        for (int kk = 0; kk < 16; kk++) {
            const ull* Ap = (const ull*)(As + kk * 128);
            const ull* Bp = (const ull*)(Bs + kk * 128);
            ull a2[4], b2[8];
#pragma unroll
            for (int p = 0; p < 4; p++) a2[p] = Ap[ty * 4 + p];
#pragma unroll
            for (int j = 0; j < 8; j++) b2[j] = Bp[tx + 16 * j];
#pragma unroll
            for (int p = 0; p < 4; p++)
#pragma unroll
                for (int j = 0; j < 8; j++) acc[p][j] = ffma2(a2[p], b2[j], acc[p][j]);
        }
        __syncthreads();
    }

#pragma unroll
    for (int j = 0; j < 8; j++) {
        int col = n0 + tx + 16 * j;
        float b = bo[col];
#pragma unroll
        for (int p = 0; p < 4; p++) {
            float lo, hi;
            unpack2(acc[p][j], lo, hi);
            int row = m0 + ty * 8 + 2 * p;
            float glo = g_gate[(size_t)row * CS + col];
            float ghi = g_gate[(size_t)(row + 1) * CS + col];
            Y[(size_t)row * CS + col]       = (lo + b) * glo;
            Y[(size_t)(row + 1) * CS + col] = (hi + b) * ghi;
        }
    }
}

// =====================================================================
extern "C" void kernel_launch(void* const* d_in, const int* in_sizes, int n_in,
                              void* d_out, int out_size)
{
    const float* s     = (const float*)d_in[0];
    const float* z     = (const float*)d_in[1];
    const void*  mask  = d_in[2];
    const float* dist  = (const float*)d_in[3];
    const float* prior = (const float*)d_in[4];
    const float* Wq = (const float*)d_in[5];  const float* bq = (const float*)d_in[6];
    const float* Wk = (const float*)d_in[7];  const float* bk = (const float*)d_in[8];
    const float* Wv = (const float*)d_in[9];  const float* bv = (const float*)d_in[10];
    const float* Wz = (const float*)d_in[11];
    const float* Wo = (const float*)d_in[12]; const float* bo = (const float*)d_in[13];
    const float* Wg = (const float*)d_in[14]; const float* bg = (const float*)d_in[15];

    float* Y = (float*)d_out;
    float* attn;
    if (out_size >= LC * CS + NH * LC * LC) {
        attn = (float*)d_out + LC * CS;      // attn region of output doubles as workspace
    } else {
        void* p = nullptr;
        cudaGetSymbolAddress(&p, g_attn_fallback);
        attn = (float*)p;
    }

    k_detect  <<<1, 256>>>((const unsigned int*)mask);
    k_proj    <<<dim3(24, 8),       256>>>(s, Wq, bq, Wk, bk, Wv, bv, Wg, bg);
    k_pairbias<<<dim3(LC, 8),       128>>>(z, mask, dist, prior, Wz, attn);
    k_qk      <<<dim3(16, 16, 16),  256>>>(attn);
    k_softmax <<<NH * LC,           128>>>(attn);
    k_av      <<<dim3(8, NH),       256>>>(attn);
    k_out     <<<dim3(6, 8),        256>>>(Wo, bo, Y);
}

// round 3
// speedup vs baseline: 1.1882x; 1.1882x over previous
#include <cuda_runtime.h>
#include <cstdint>

#define LC 1024
#define CS 768
#define NH 16
#define DH 48
#define CP 128

typedef unsigned long long ull;

// ---- scratch (device globals) ----
__device__ float g_Q[LC * CS];
__device__ float g_K[LC * CS];
__device__ float g_V[LC * CS];
__device__ float g_gate[LC * CS];
__device__ float g_ctx[LC * CS];
__device__ float g_attn_fallback[NH * LC * LC];
__device__ int   g_mask_is_u8;

// ---- f32x2 helpers ----
__device__ __forceinline__ ull ffma2(ull a, ull b, ull c) {
    ull d;
    asm("fma.rn.f32x2 %0,%1,%2,%3;" : "=l"(d) : "l"(a), "l"(b), "l"(c));
    return d;
}
__device__ __forceinline__ ull pack2(float lo, float hi) {
    ull r;
    asm("mov.b64 %0,{%1,%2};" : "=l"(r) : "f"(lo), "f"(hi));
    return r;
}
__device__ __forceinline__ void unpack2(ull v, float& lo, float& hi) {
    asm("mov.b64 {%0,%1},%2;" : "=f"(lo), "=f"(hi) : "l"(v));
}

// =====================================================================
// K0: mask dtype detector (int32 bool words are all 0/1; u8-packed aren't)
// =====================================================================
__global__ void k_detect(const unsigned int* __restrict__ m)
{
    __shared__ int s;
    if (threadIdx.x == 0) s = 0;
    __syncthreads();
    int bad = 0;
    for (int i = threadIdx.x; i < 1024; i += blockDim.x)
        if (m[i] > 1u) bad = 1;
    if (bad) atomicOr(&s, 1);
    __syncthreads();
    if (threadIdx.x == 0) g_mask_is_u8 = s;
}

// =====================================================================
// K1: fused projections  X = S @ [Wq|Wk|Wv|Wg] + bias
// tile 64(M)x128(N), 128 thr (16tx x 8ty), micro 8x8, grid (24, 16)
// =====================================================================
__global__ void __launch_bounds__(128) k_proj(
    const float* __restrict__ S,
    const float* __restrict__ Wq, const float* __restrict__ bq,
    const float* __restrict__ Wk, const float* __restrict__ bk,
    const float* __restrict__ Wv, const float* __restrict__ bv,
    const float* __restrict__ Wg, const float* __restrict__ bg)
{
    __shared__ __align__(16) float  As[16 * 64];    // [kk][m]
    __shared__ __align__(16) float2 Bs[16 * 128];   // [kk][n] duplicated

    int bn = blockIdx.x;
    int wi = bn / 6;
    int n0 = (bn % 6) * 128;
    int m0 = blockIdx.y * 64;

    const float* W   = wi == 0 ? Wq : wi == 1 ? Wk : wi == 2 ? Wv : Wg;
    const float* bb  = wi == 0 ? bq : wi == 1 ? bk : wi == 2 ? bv : bg;
    float*       dst = wi == 0 ? g_Q : wi == 1 ? g_K : wi == 2 ? g_V : g_gate;

    int t = threadIdx.x, tx = t & 15, ty = t >> 4;

    ull acc[4][8];
#pragma unroll
    for (int p = 0; p < 4; p++)
#pragma unroll
        for (int j = 0; j < 8; j++) acc[p][j] = 0ull;

    for (int k0 = 0; k0 < CS; k0 += 16) {
#pragma unroll
        for (int l = 0; l < 2; l++) {
            int idx = l * 128 + t, row = idx >> 2, q = idx & 3;
            float4 v = *(const float4*)(S + (size_t)(m0 + row) * CS + k0 + q * 4);
            As[(q * 4 + 0) * 64 + row] = v.x;
            As[(q * 4 + 1) * 64 + row] = v.y;
            As[(q * 4 + 2) * 64 + row] = v.z;
            As[(q * 4 + 3) * 64 + row] = v.w;
        }
#pragma unroll
        for (int l = 0; l < 4; l++) {
            int idx = l * 128 + t, kk = idx >> 5, q = idx & 31;
            float4 v = *(const float4*)(W + (size_t)(k0 + kk) * CS + n0 + q * 4);
            Bs[kk * 128 + q * 4 + 0] = make_float2(v.x, v.x);
            Bs[kk * 128 + q * 4 + 1] = make_float2(v.y, v.y);
            Bs[kk * 128 + q * 4 + 2] = make_float2(v.z, v.z);
            Bs[kk * 128 + q * 4 + 3] = make_float2(v.w, v.w);
        }
        __syncthreads();
#pragma unroll
        for (int kk = 0; kk < 16; kk++) {
            const ull* Ap = (const ull*)(As + kk * 64);
            const ull* Bp = (const ull*)(Bs + kk * 128);
            ull a2[4], b2[8];
#pragma unroll
            for (int p = 0; p < 4; p++) a2[p] = Ap[ty * 4 + p];
#pragma unroll
            for (int j = 0; j < 8; j++) b2[j] = Bp[tx + 16 * j];
#pragma unroll
            for (int p = 0; p < 4; p++)
#pragma unroll
                for (int j = 0; j < 8; j++) acc[p][j] = ffma2(a2[p], b2[j], acc[p][j]);
        }
        __syncthreads();
    }

#pragma unroll
    for (int j = 0; j < 8; j++) {
        int col = n0 + tx + 16 * j;
        float b = bb[col];
#pragma unroll
        for (int p = 0; p < 4; p++) {
            float lo, hi;
            unpack2(acc[p][j], lo, hi);
            lo += b; hi += b;
            if (wi == 3) {
                lo = 1.f / (1.f + __expf(-lo));
                hi = 1.f / (1.f + __expf(-hi));
            }
            int row = m0 + ty * 8 + 2 * p;
            dst[(size_t)row * CS + col]       = lo;
            dst[(size_t)(row + 1) * CS + col] = hi;
        }
    }
}

// =====================================================================
// K2: base logits = z@Wz + dist + prior, masked, layout [h][i][j]
// =====================================================================
__global__ void __launch_bounds__(128) k_pairbias(
    const float* __restrict__ z, const void* __restrict__ maskp,
    const float* __restrict__ dist, const float* __restrict__ prior,
    const float* __restrict__ Wz, float* __restrict__ A)
{
    __shared__ __align__(16) float2 w2[128 * 8];
    __shared__ float tr[16][128];

    int i = blockIdx.x, jt = blockIdx.y;
    int t = threadIdx.x;
    int j = jt * 128 + t;

    {
        const float4* wz4 = (const float4*)(Wz + t * 16);
        float4 a = wz4[0], b = wz4[1], c = wz4[2], d = wz4[3];
        w2[t * 8 + 0] = make_float2(a.x, a.y);
        w2[t * 8 + 1] = make_float2(a.z, a.w);
        w2[t * 8 + 2] = make_float2(b.x, b.y);
        w2[t * 8 + 3] = make_float2(b.z, b.w);
        w2[t * 8 + 4] = make_float2(c.x, c.y);
        w2[t * 8 + 5] = make_float2(c.z, c.w);
        w2[t * 8 + 6] = make_float2(d.x, d.y);
        w2[t * 8 + 7] = make_float2(d.z, d.w);
    }
    __syncthreads();

    ull acc[8];
#pragma unroll
    for (int hp = 0; hp < 8; hp++) acc[hp] = 0ull;

    const float4* zp = (const float4*)(z + ((size_t)i * LC + j) * CP);
    const ull* wp = (const ull*)w2;
#pragma unroll 8
    for (int c4 = 0; c4 < 32; c4++) {
        float4 v = zp[c4];
        float vs[4] = {v.x, v.y, v.z, v.w};
#pragma unroll
        for (int u = 0; u < 4; u++) {
            ull zz = pack2(vs[u], vs[u]);
            const ull* wrow = wp + (c4 * 4 + u) * 8;
#pragma unroll
            for (int hp = 0; hp < 8; hp++) acc[hp] = ffma2(zz, wrow[hp], acc[hp]);
        }
    }

    int ij = i * LC + j;
    float bias[16];
#pragma unroll
    for (int hp = 0; hp < 8; hp++) unpack2(acc[hp], bias[2 * hp], bias[2 * hp + 1]);

    const float4* dv = (const float4*)(dist + (size_t)ij * 16);
    float4 d0 = dv[0], d1 = dv[1], d2 = dv[2], d3 = dv[3];
    float db[16] = {d0.x, d0.y, d0.z, d0.w, d1.x, d1.y, d1.z, d1.w,
                    d2.x, d2.y, d2.z, d2.w, d3.x, d3.y, d3.z, d3.w};
    float pr = prior[ij];

    bool mv;
    if (g_mask_is_u8)
        mv = ((const unsigned char*)maskp)[ij] != 0;
    else
        mv = ((const int*)maskp)[ij] != 0;

#pragma unroll
    for (int hh = 0; hh < 16; hh++) {
        float vv = bias[hh] + db[hh] + pr;
        tr[hh][t] = mv ? vv : -1e30f;
    }
    __syncthreads();
#pragma unroll
    for (int hh = 0; hh < 16; hh++)
        A[((size_t)hh * LC + i) * LC + jt * 128 + t] = tr[hh][t];
}

// =====================================================================
// K3a: logits += scale * Q_h K_h^T; tile 128x128, 256 thr, micro 8x8,
// K-dim 48 loaded once. Dynamic smem: Qs 24KB + Ks(dup) 48KB = 72KB.
// grid (8, 8, 16) = 1024 blocks
// =====================================================================
#define QK_SCALE 0.14433756729740643f   // 1/sqrt(48)

__global__ void __launch_bounds__(256) k_qk(float* __restrict__ A)
{
    extern __shared__ __align__(16) float sm_qk[];
    float*  Qs = sm_qk;                       // [48][128]
    float2* Ks = (float2*)(sm_qk + 48 * 128); // [48][128] dup

    int j0 = blockIdx.x * 128, i0 = blockIdx.y * 128, h = blockIdx.z;
    int t = threadIdx.x, tx = t & 15, ty = t >> 4;

#pragma unroll
    for (int l = 0; l < 6; l++) {
        int idx = l * 256 + t;          // 0..1535 float4 slots
        int row = idx / 12, q = idx - row * 12;
        float4 v = *(const float4*)(g_Q + (size_t)(i0 + row) * CS + h * DH + q * 4);
        Qs[(q * 4 + 0) * 128 + row] = v.x * QK_SCALE;
        Qs[(q * 4 + 1) * 128 + row] = v.y * QK_SCALE;
        Qs[(q * 4 + 2) * 128 + row] = v.z * QK_SCALE;
        Qs[(q * 4 + 3) * 128 + row] = v.w * QK_SCALE;
        float4 w = *(const float4*)(g_K + (size_t)(j0 + row) * CS + h * DH + q * 4);
        Ks[(q * 4 + 0) * 128 + row] = make_float2(w.x, w.x);
        Ks[(q * 4 + 1) * 128 + row] = make_float2(w.y, w.y);
        Ks[(q * 4 + 2) * 128 + row] = make_float2(w.z, w.z);
        Ks[(q * 4 + 3) * 128 + row] = make_float2(w.w, w.w);
    }
    __syncthreads();

    ull acc[4][8];
#pragma unroll
    for (int p = 0; p < 4; p++)
#pragma unroll
        for (int j = 0; j < 8; j++) acc[p][j] = 0ull;

#pragma unroll 12
    for (int kk = 0; kk < 48; kk++) {
        const ull* Ap = (const ull*)(Qs + kk * 128);
        const ull* Bp = (const ull*)(Ks + kk * 128);
        ull a2[4], b2[8];
#pragma unroll
        for (int p = 0; p < 4; p++) a2[p] = Ap[ty * 4 + p];
#pragma unroll
        for (int j = 0; j < 8; j++) b2[j] = Bp[tx + 16 * j];
#pragma unroll
        for (int p = 0; p < 4; p++)
#pragma unroll
            for (int j = 0; j < 8; j++) acc[p][j] = ffma2(a2[p], b2[j], acc[p][j]);
    }

#pragma unroll
    for (int p = 0; p < 4; p++) {
        int r0 = i0 + ty * 8 + 2 * p;
        float* C0 = A + ((size_t)h * LC + r0) * LC;
        float* C1 = C0 + LC;
#pragma unroll
        for (int j = 0; j < 8; j++) {
            int col = j0 + tx + 16 * j;
            float lo, hi;
            unpack2(acc[p][j], lo, hi);
            C0[col] += lo;
            C1[col] += hi;
        }
    }
}

// =====================================================================
// K3b: rowwise softmax in place
// =====================================================================
__global__ void __launch_bounds__(128) k_softmax(float* __restrict__ A)
{
    size_t r = blockIdx.x;
    float* row = A + r * LC;
    int t = threadIdx.x;
    float4 v0 = ((float4*)row)[2 * t], v1 = ((float4*)row)[2 * t + 1];

    float mx = fmaxf(fmaxf(fmaxf(v0.x, v0.y), fmaxf(v0.z, v0.w)),
                     fmaxf(fmaxf(v1.x, v1.y), fmaxf(v1.z, v1.w)));
#pragma unroll
    for (int o = 16; o; o >>= 1) mx = fmaxf(mx, __shfl_xor_sync(0xffffffffu, mx, o));
    __shared__ float sm[4], ss[4];
    if ((t & 31) == 0) sm[t >> 5] = mx;
    __syncthreads();
    mx = fmaxf(fmaxf(sm[0], sm[1]), fmaxf(sm[2], sm[3]));

    v0.x = __expf(v0.x - mx); v0.y = __expf(v0.y - mx);
    v0.z = __expf(v0.z - mx); v0.w = __expf(v0.w - mx);
    v1.x = __expf(v1.x - mx); v1.y = __expf(v1.y - mx);
    v1.z = __expf(v1.z - mx); v1.w = __expf(v1.w - mx);
    float s = v0.x + v0.y + v0.z + v0.w + v1.x + v1.y + v1.z + v1.w;
#pragma unroll
    for (int o = 16; o; o >>= 1) s += __shfl_xor_sync(0xffffffffu, s, o);
    if ((t & 31) == 0) ss[t >> 5] = s;
    __syncthreads();
    s = ss[0] + ss[1] + ss[2] + ss[3];

    float inv = 1.f / s;
    v0.x *= inv; v0.y *= inv; v0.z *= inv; v0.w *= inv;
    v1.x *= inv; v1.y *= inv; v1.z *= inv; v1.w *= inv;
    ((float4*)row)[2 * t] = v0;
    ((float4*)row)[2 * t + 1] = v1;
}

// =====================================================================
// K4: ctx = attn @ V per head. tile 64 rows x 48 cols, j chunks 32,
// 128 thr (16tx x 8ty), micro 8 rows x 3 cols. grid (16, 16)
// =====================================================================
__global__ void __launch_bounds__(128) k_av(const float* __restrict__ A)
{
    __shared__ __align__(16) float  As[32 * 64];   // [j][i]
    __shared__ __align__(16) float2 Vs[32 * 48];   // [j][d] dup

    int i0 = blockIdx.x * 64, h = blockIdx.y;
    int t = threadIdx.x, tx = t & 15, ty = t >> 4;

    ull acc[4][3];
#pragma unroll
    for (int p = 0; p < 4; p++)
#pragma unroll
        for (int c = 0; c < 3; c++) acc[p][c] = 0ull;

    for (int j0 = 0; j0 < LC; j0 += 32) {
#pragma unroll
        for (int l = 0; l < 4; l++) {
            int idx = l * 128 + t, row = idx >> 3, q = idx & 7;
            float4 v = *(const float4*)(A + ((size_t)h * LC + i0 + row) * LC + j0 + q * 4);
            As[(q * 4 + 0) * 64 + row] = v.x;
            As[(q * 4 + 1) * 64 + row] = v.y;
            As[(q * 4 + 2) * 64 + row] = v.z;
            As[(q * 4 + 3) * 64 + row] = v.w;
        }
#pragma unroll
        for (int l = 0; l < 3; l++) {
            int idx = l * 128 + t;      // 0..383 float4 slots
            int jj = idx / 12, q = idx - jj * 12;
            float4 v = *(const float4*)(g_V + (size_t)(j0 + jj) * CS + h * DH + q * 4);
            Vs[jj * 48 + q * 4 + 0] = make_float2(v.x, v.x);
            Vs[jj * 48 + q * 4 + 1] = make_float2(v.y, v.y);
            Vs[jj * 48 + q * 4 + 2] = make_float2(v.z, v.z);
            Vs[jj * 48 + q * 4 + 3] = make_float2(v.w, v.w);
        }
        __syncthreads();
#pragma unroll
        for (int kk = 0; kk < 32; kk++) {
            const ull* Ap = (const ull*)(As + kk * 64);
            const ull* Vp = (const ull*)(Vs + kk * 48);
            ull a2[4], b2[3];
#pragma unroll
            for (int p = 0; p < 4; p++) a2[p] = Ap[ty * 4 + p];
#pragma unroll
            for (int c = 0; c < 3; c++) b2[c] = Vp[tx * 3 + c];
#pragma unroll
            for (int p = 0; p < 4; p++)
#pragma unroll
                for (int c = 0; c < 3; c++) acc[p][c] = ffma2(a2[p], b2[c], acc[p][c]);
        }
        __syncthreads();
    }

#pragma unroll
    for (int p = 0; p < 4; p++) {
        int r = i0 + ty * 8 + 2 * p;
#pragma unroll
        for (int c = 0; c < 3; c++) {
            float lo, hi;
            unpack2(acc[p][c], lo, hi);
            g_ctx[(size_t)r * CS + h * DH + tx * 3 + c]       = lo;
            g_ctx[(size_t)(r + 1) * CS + h * DH + tx * 3 + c] = hi;
        }
    }
}

// =====================================================================
// K5: y = gate * (ctx @ Wo + bo). tile 64x64, 128 thr, micro 8x4,
// grid (12, 16) = 192 blocks
// =====================================================================
__global__ void __launch_bounds__(128) k_out(
    const float* __restrict__ Wo, const float* __restrict__ bo, float* __restrict__ Y)
{
    __shared__ __align__(16) float  As[16 * 64];
    __shared__ __align__(16) float2 Bs[16 * 64];

    int n0 = blockIdx.x * 64;
    int m0 = blockIdx.y * 64;
    int t = threadIdx.x, tx = t & 15, ty = t >> 4;

    ull acc[4][4];
#pragma unroll
    for (int p = 0; p < 4; p++)
#pragma unroll
        for (int c = 0; c < 4; c++) acc[p][c] = 0ull;

    for (int k0 = 0; k0 < CS; k0 += 16) {
#pragma unroll
        for (int l = 0; l < 2; l++) {
            int idx = l * 128 + t, row = idx >> 2, q = idx & 3;
            float4 v = *(const float4*)(g_ctx + (size_t)(m0 + row) * CS + k0 + q * 4);
            As[(q * 4 + 0) * 64 + row] = v.x;
            As[(q * 4 + 1) * 64 + row] = v.y;
            As[(q * 4 + 2) * 64 + row] = v.z;
            As[(q * 4 + 3) * 64 + row] = v.w;
        }
#pragma unroll
        for (int l = 0; l < 2; l++) {
            int idx = l * 128 + t, kk = idx >> 4, q = idx & 15;
            float4 v = *(const float4*)(Wo + (size_t)(k0 + kk) * CS + n0 + q * 4);
            Bs[kk * 64 + q * 4 + 0] = make_float2(v.x, v.x);
            Bs[kk * 64 + q * 4 + 1] = make_float2(v.y, v.y);
            Bs[kk * 64 + q * 4 + 2] = make_float2(v.z, v.z);
            Bs[kk * 64 + q * 4 + 3] = make_float2(v.w, v.w);
        }
        __syncthreads();
#pragma unroll
        for (int kk = 0; kk < 16; kk++) {
            const ull* Ap = (const ull*)(As + kk * 64);
            const ull* Bp = (const ull*)(Bs + kk * 64);
            ull a2[4], b2[4];
#pragma unroll
            for (int p = 0; p < 4; p++) a2[p] = Ap[ty * 4 + p];
#pragma unroll
            for (int c = 0; c < 4; c++) b2[c] = Bp[tx + 16 * c];
#pragma unroll
            for (int p = 0; p < 4; p++)
#pragma unroll
                for (int c = 0; c < 4; c++) acc[p][c] = ffma2(a2[p], b2[c], acc[p][c]);
        }
        __syncthreads();
    }

#pragma unroll
    for (int c = 0; c < 4; c++) {
        int col = n0 + tx + 16 * c;
        float b = bo[col];
#pragma unroll
        for (int p = 0; p < 4; p++) {
            float lo, hi;
            unpack2(acc[p][c], lo, hi);
            int row = m0 + ty * 8 + 2 * p;
            float glo = g_gate[(size_t)row * CS + col];
            float ghi = g_gate[(size_t)(row + 1) * CS + col];
            Y[(size_t)row * CS + col]       = (lo + b) * glo;
            Y[(size_t)(row + 1) * CS + col] = (hi + b) * ghi;
        }
    }
}

// =====================================================================
extern "C" void kernel_launch(void* const* d_in, const int* in_sizes, int n_in,
                              void* d_out, int out_size)
{
    const float* s     = (const float*)d_in[0];
    const float* z     = (const float*)d_in[1];
    const void*  mask  = d_in[2];
    const float* dist  = (const float*)d_in[3];
    const float* prior = (const float*)d_in[4];
    const float* Wq = (const float*)d_in[5];  const float* bq = (const float*)d_in[6];
    const float* Wk = (const float*)d_in[7];  const float* bk = (const float*)d_in[8];
    const float* Wv = (const float*)d_in[9];  const float* bv = (const float*)d_in[10];
    const float* Wz = (const float*)d_in[11];
    const float* Wo = (const float*)d_in[12]; const float* bo = (const float*)d_in[13];
    const float* Wg = (const float*)d_in[14]; const float* bg = (const float*)d_in[15];

    float* Y = (float*)d_out;
    float* attn;
    if (out_size >= LC * CS + NH * LC * LC) {
        attn = (float*)d_out + LC * CS;
    } else {
        void* p = nullptr;
        cudaGetSymbolAddress(&p, g_attn_fallback);
        attn = (float*)p;
    }

    const int qk_smem = 48 * 128 * 4 + 48 * 128 * 8;   // 73728 bytes
    cudaFuncSetAttribute(k_qk, cudaFuncAttributeMaxDynamicSharedMemorySize, qk_smem);

    k_detect  <<<1, 256>>>((const unsigned int*)mask);
    k_proj    <<<dim3(24, 16),          128>>>(s, Wq, bq, Wk, bk, Wv, bv, Wg, bg);
    k_pairbias<<<dim3(LC, 8),           128>>>(z, mask, dist, prior, Wz, attn);
    k_qk      <<<dim3(8, 8, 16), 256, qk_smem>>>(attn);
    k_softmax <<<NH * LC,               128>>>(attn);
    k_av      <<<dim3(16, NH),          128>>>(attn);
    k_out     <<<dim3(12, 16),          128>>>(Wo, bo, Y);
}